// round 2
// baseline (speedup 1.0000x reference)
#include <cuda_runtime.h>

// ---------------- static device scratch ----------------
__device__ float g_h[16*64*512];
__device__ float g_r[16*64*512];
__device__ float g_kbias[16*256*512];
__device__ float g_bt[192*24576];
__device__ float g_kern[201326592];   // 8192 x 24576 (m = b*512+l, ch)
__device__ float g_cb[16*32*4096];

__device__ __forceinline__ float lrelu(float v){ return v>=0.f ? v : 0.2f*v; }

// ---------------- generic small conv1d over L=512 ----------------
// out[b,co,l] = (lrelu?)(bias[co] + sum_{ci,k} in[b,ci,l+k-PAD]*w[co,ci,k]) (+skip)
template<int CI,int KS,bool RELU,bool SKIP>
__global__ void conv1d_small(const float* __restrict__ in,const float* __restrict__ w,
    const float* __restrict__ bias,const float* __restrict__ skip,
    float* __restrict__ out,int Cout){
  const int PAD=(KS-1)/2, WDT=64+KS-1;
  const int l0=blockIdx.x*64, cg=blockIdx.y, b=blockIdx.z;
  __shared__ float s[CI][WDT];
  for(int idx=threadIdx.x; idx<CI*WDT; idx+=256){
    int ci=idx/WDT, p=idx-ci*WDT, l=l0+p-PAD;
    s[ci][p]=(l>=0&&l<512)?in[(b*CI+ci)*512+l]:0.f;
  }
  __syncthreads();
  const int co=cg*64+(threadIdx.x>>2), ls=(threadIdx.x&3)*16;
  float acc[16]; float bz=bias[co];
#pragma unroll
  for(int j=0;j<16;j++)acc[j]=bz;
  const float* wr=w+(size_t)co*CI*KS;
  for(int ci=0;ci<CI;ci++){
    float xv[16+KS-1];
#pragma unroll
    for(int j=0;j<16+KS-1;j++)xv[j]=s[ci][ls+j];
#pragma unroll
    for(int k=0;k<KS;k++){
      float wv=__ldg(&wr[ci*KS+k]);
#pragma unroll
      for(int j=0;j<16;j++)acc[j]=fmaf(wv,xv[j+k],acc[j]);
    }
  }
  float* orow=out+((size_t)b*Cout+co)*512+l0+ls;
  const float* srow=SKIP?(skip+((size_t)b*Cout+co)*512+l0+ls):nullptr;
#pragma unroll
  for(int j=0;j<16;j++){
    float v=acc[j];
    if(RELU)v=lrelu(v);
    if(SKIP)v+=srow[j];
    orow[j]=v;
  }
}

// ---------------- transpose ker_w (24576 x 192) -> g_bt[kk][ch] ----------------
__global__ void transpose_kw(const float* __restrict__ kw){
  __shared__ float tile[32][33];
  int c0=blockIdx.x*32, k0=blockIdx.y*32, tx=threadIdx.x, ty=threadIdx.y;
  for(int i=ty;i<32;i+=8) tile[i][tx]=kw[(size_t)(c0+i)*192+k0+tx];
  __syncthreads();
  for(int i=ty;i<32;i+=8) g_bt[(size_t)(k0+i)*24576+c0+tx]=tile[tx][i];
}

// ---------------- big GEMM: kern[m,ch] = sum_kk A[m,kk]*g_bt[kk,ch] + ker_b ----------
// A[m,kk]: m=(b,l), kk=hid*3+t -> h[b,hid,l+t-1] (zero-padded)
__global__ void __launch_bounds__(256,2) kern_gemm(const float* __restrict__ kerb){
  const int n0=blockIdx.x*128, m0=blockIdx.y*128;
  const int b=m0>>9, l0=m0&511;
  __shared__ float As[2][16][128], Bs[2][16][128];
  const int tid=threadIdx.x, tx=tid&15, ty=tid>>4;
  unsigned long long acc[8][4];
#pragma unroll
  for(int i=0;i<8;i++)
#pragma unroll
    for(int j=0;j<4;j++)acc[i][j]=0ull;
#pragma unroll
  for(int r=0;r<8;r++){
    int idx=tid+r*256, kr=idx>>7, mm=idx&127;
    int hid=kr/3, t3=kr-hid*3, l=l0+mm+t3-1;
    As[0][kr][mm]=(l>=0&&l<512)?g_h[(b*64+hid)*512+l]:0.f;
    Bs[0][kr][mm]=g_bt[(size_t)kr*24576+n0+mm];
  }
  __syncthreads();
  for(int c=0;c<12;c++){
    float rA[8],rB[8];
    if(c<11){
#pragma unroll
      for(int r=0;r<8;r++){
        int idx=tid+r*256, kr=idx>>7, mm=idx&127, kk=(c+1)*16+kr;
        int hid=kk/3, t3=kk-hid*3, l=l0+mm+t3-1;
        rA[r]=(l>=0&&l<512)?g_h[(b*64+hid)*512+l]:0.f;
        rB[r]=g_bt[(size_t)kk*24576+n0+mm];
      }
    }
    float (*A)[128]=As[c&1];
    float (*Bm)[128]=Bs[c&1];
#pragma unroll
    for(int kk=0;kk<16;kk++){
      float4 a0=*(const float4*)&A[kk][ty*8];
      float4 a1=*(const float4*)&A[kk][ty*8+4];
      float av[8]={a0.x,a0.y,a0.z,a0.w,a1.x,a1.y,a1.z,a1.w};
      unsigned long long a2[8], bv[4];
#pragma unroll
      for(int mi=0;mi<8;mi++){
        unsigned u=__float_as_uint(av[mi]);
        asm("mov.b64 %0,{%1,%2};":"=l"(a2[mi]):"r"(u),"r"(u));
      }
#pragma unroll
      for(int nj=0;nj<4;nj++) bv[nj]=*(const unsigned long long*)&Bm[kk][nj*32+tx*2];
#pragma unroll
      for(int mi=0;mi<8;mi++)
#pragma unroll
        for(int nj=0;nj<4;nj++)
          asm("fma.rn.f32x2 %0,%1,%2,%0;":"+l"(acc[mi][nj]):"l"(a2[mi]),"l"(bv[nj]));
    }
    if(c<11){
      int nb=(c+1)&1;
#pragma unroll
      for(int r=0;r<8;r++){
        int idx=tid+r*256;
        As[nb][idx>>7][idx&127]=rA[r];
        Bs[nb][idx>>7][idx&127]=rB[r];
      }
    }
    __syncthreads();
  }
#pragma unroll
  for(int mi=0;mi<8;mi++){
    size_t m=(size_t)m0+ty*8+mi;
    float* crow=g_kern+m*24576+n0;
#pragma unroll
    for(int nj=0;nj<4;nj++){
      int col=nj*32+tx*2; unsigned lo,hi;
      asm("mov.b64 {%0,%1},%2;":"=r"(lo),"=r"(hi):"l"(acc[mi][nj]));
      float2 v;
      v.x=__uint_as_float(lo)+kerb[n0+col];
      v.y=__uint_as_float(hi)+kerb[n0+col+1];
      *(float2*)&crow[col]=v;
    }
  }
}

// ---------------- convt_pre: lrelu(x) -> ConvTranspose1d(k=16, s=8, p=4) --------
// out[b,co,t] = ctb[co] + sum_ci lx[s]*ctw[ci,co,15-k0] + lx[s+1]*ctw[ci,co,7-k0]
// k0 = (11-t) mod 8, s = (t+k0-11)/8
__global__ void convt_pre_k(const float* __restrict__ x,const float* __restrict__ ctw,
    const float* __restrict__ ctb,float* __restrict__ xx){
  const int b=blockIdx.z, cg=blockIdx.y, t0=blockIdx.x*64, tid=threadIdx.x;
  __shared__ float swt[2048];     // [co_l][ci][16]
  __shared__ float sx[32][12];
  for(int idx=tid;idx<2048;idx+=256){
    int co_l=idx>>9, ci=(idx>>4)&31, kk=idx&15;
    swt[idx]=ctw[(ci*32+cg*4+co_l)*16+kk];
  }
  const int sbase=(t0>>3)-2;
  for(int idx=tid;idx<384;idx+=256){
    int ci=idx/12, j=idx-ci*12, sp=sbase+j;
    sx[ci][j]=(sp>=0&&sp<512)?lrelu(x[(b*32+ci)*512+sp]):0.f;
  }
  __syncthreads();
  const int co_l=tid>>6, t=t0+(tid&63), co=cg*4+co_l;
  const int k0=(8+(11-t)%8)&7;
  const int j=((t+k0-11)>>3)-sbase;
  float acc=ctb[co];
  const float* wl=&swt[co_l*512];
#pragma unroll 8
  for(int ci=0;ci<32;ci++)
    acc+=sx[ci][j]*wl[ci*16+15-k0]+sx[ci][j+1]*wl[ci*16+7-k0];
  xx[(b*32+co)*4096+t]=acc;
}

// ---------------- dilated conv block: g_cb = lrelu(conv(lrelu(xx))) ----------------
__global__ void conv_block_k(const float* __restrict__ xx,const float* __restrict__ w,
    const float* __restrict__ bias,int dil){
  const int b=blockIdx.z, t0=blockIdx.x*128, tid=threadIdx.x;
  __shared__ float sx[32*182];
  const int W=128+2*dil;
  for(int idx=tid;idx<32*W;idx+=256){
    int ci=idx/W, p=idx-ci*W, t=t0+p-dil;
    sx[ci*182+p]=(t>=0&&t<4096)?lrelu(xx[(b*32+ci)*4096+t]):0.f;
  }
  __syncthreads();
  const int co=tid>>3, lt=(tid&7)*16;
  float acc[16]; float bz=bias[co];
#pragma unroll
  for(int j=0;j<16;j++)acc[j]=bz;
  for(int ci=0;ci<32;ci++){
    float w0=__ldg(&w[(co*32+ci)*3]);
    float w1=__ldg(&w[(co*32+ci)*3+1]);
    float w2=__ldg(&w[(co*32+ci)*3+2]);
    const float* sr=&sx[ci*182+lt];
#pragma unroll
    for(int j=0;j<16;j++)
      acc[j]+=w0*sr[j]+w1*sr[j+dil]+w2*sr[j+2*dil];
  }
  float* orow=&g_cb[(b*32+co)*4096+t0+lt];
#pragma unroll
  for(int j=0;j<16;j++)orow[j]=lrelu(acc[j]);
}

// ---------------- LVC einsum + gated residual update (one block per (b,l)) ---------
__global__ void einsum_gate_k(const float* __restrict__ kbias,float* __restrict__ xx,int layer){
  const int l=blockIdx.x, b=blockIdx.y, tid=threadIdx.x;
  __shared__ __align__(16) float sk[6144];
  __shared__ float sx[32][10];
  __shared__ float so[64][8];
  const float4* kp=(const float4*)(g_kern+((size_t)(b*512+l))*24576+layer*6144);
#pragma unroll
  for(int i=0;i<6;i++) ((float4*)sk)[tid+i*256]=kp[tid+i*256];
  for(int i=tid;i<320;i+=256){
    int ci=i/10, j=i-ci*10, t=l*8+j-1;
    sx[ci][j]=(t>=0&&t<4096)?g_cb[(b*32+ci)*4096+t]:0.f;
  }
  __syncthreads();
  const int o=tid>>2, h2=(tid&3)*2;
  float a0=0.f,a1=0.f;
#pragma unroll 4
  for(int ci=0;ci<32;ci++){
    const float* kb=&sk[ci*192+o*3];
    const float* xr=&sx[ci][h2];
    a0+=xr[0]*kb[0]+xr[1]*kb[1]+xr[2]*kb[2];
    a1+=xr[1]*kb[0]+xr[2]*kb[1]+xr[3]*kb[2];
  }
  const float bb=kbias[((b*4+layer)*64+o)*512+l];
  so[o][h2]=a0+bb; so[o][h2+1]=a1+bb;
  __syncthreads();
  const int co=tid>>3, h=tid&7;
  float g=1.f/(1.f+__expf(-so[co][h]));
  float th=tanhf(so[co+32][h]);
  xx[(b*32+co)*4096+l*8+h]+=g*th;
}

extern "C" void kernel_launch(void* const* d_in,const int* in_sizes,int n_in,
                              void* d_out,int out_size){
  const float* x     =(const float*)d_in[0];
  const float* c     =(const float*)d_in[1];
  const float* in_w  =(const float*)d_in[2];
  const float* in_b  =(const float*)d_in[3];
  const float* res_ws=(const float*)d_in[4];
  const float* res_bs=(const float*)d_in[5];
  const float* ker_w =(const float*)d_in[6];
  const float* ker_b =(const float*)d_in[7];
  const float* bias_w=(const float*)d_in[8];
  const float* bias_b=(const float*)d_in[9];
  const float* ct_w  =(const float*)d_in[10];
  const float* ct_b  =(const float*)d_in[11];
  const float* cb_ws =(const float*)d_in[12];
  const float* cb_bs =(const float*)d_in[13];
  float* xx=(float*)d_out;
  float *ph,*pr,*pkb;
  cudaGetSymbolAddress((void**)&ph, g_h);
  cudaGetSymbolAddress((void**)&pr, g_r);
  cudaGetSymbolAddress((void**)&pkb,g_kbias);

  // kernel predictor trunk
  conv1d_small<100,5,true,false><<<dim3(8,1,16),256>>>(c,in_w,in_b,nullptr,ph,64);
  for(int j=0;j<3;j++){
    conv1d_small<64,3,true,false><<<dim3(8,1,16),256>>>(
        ph,res_ws+(size_t)(j*2)*12288,res_bs+(size_t)(j*2)*64,nullptr,pr,64);
    conv1d_small<64,3,true,true><<<dim3(8,1,16),256>>>(
        pr,res_ws+(size_t)(j*2+1)*12288,res_bs+(size_t)(j*2+1)*64,ph,ph,64);
  }
  // bias head
  conv1d_small<64,3,false,false><<<dim3(8,4,16),256>>>(ph,bias_w,bias_b,nullptr,pkb,256);
  // kernel head as GEMM
  transpose_kw<<<dim3(768,6),dim3(32,8)>>>(ker_w);
  kern_gemm<<<dim3(192,64),256>>>(ker_b);
  // upsample
  convt_pre_k<<<dim3(64,8,16),256>>>(x,ct_w,ct_b,xx);
  // 4 LVC layers
  const int dils[4]={1,3,9,27};
  for(int i=0;i<4;i++){
    conv_block_k<<<dim3(32,1,16),256>>>(xx,cb_ws+(size_t)i*3072,cb_bs+(size_t)i*32,dils[i]);
    einsum_gate_k<<<dim3(512,16),256>>>(pkb,xx,i);
  }
}

// round 4
// speedup vs baseline: 1.4361x; 1.4361x over previous
#include <cuda_runtime.h>
#include <cuda_bf16.h>
#include <cstdint>

// ---------------- static device scratch ----------------
__device__ float g_h[16*64*512];
__device__ float g_r[16*64*512];
__device__ float g_kbias[16*256*512];
__device__ float g_kern[201326592];   // 8192 x 24576 (m = b*512+l, ch)
__device__ float g_cb[16*32*4096];
__device__ __nv_bfloat16 g_a16[8192*576];    // A' = [Ah|Ah|Al]
__device__ __nv_bfloat16 g_b16[24576*576];   // B' = [Bh|Bl|Bh]

__device__ __forceinline__ float lrelu(float v){ return v>=0.f ? v : 0.2f*v; }

__device__ __forceinline__ uint32_t smem_u32(const void* p){
  uint32_t a;
  asm("{ .reg .u64 t; cvta.to.shared.u64 t, %1; cvt.u32.u64 %0, t; }":"=r"(a):"l"(p));
  return a;
}
__device__ __forceinline__ void cp16(uint32_t d, const void* s){
  asm volatile("cp.async.cg.shared.global [%0], [%1], 16;"::"r"(d),"l"(s));
}
__device__ __forceinline__ void ldmx4(uint32_t* r, uint32_t a){
  asm volatile("ldmatrix.sync.aligned.m8n8.x4.shared.b16 {%0,%1,%2,%3},[%4];"
    :"=r"(r[0]),"=r"(r[1]),"=r"(r[2]),"=r"(r[3]):"r"(a));
}
__device__ __forceinline__ void mma16816(float* c, const uint32_t* a, uint32_t b0, uint32_t b1){
  asm volatile("mma.sync.aligned.m16n8k16.row.col.f32.bf16.bf16.f32 "
    "{%0,%1,%2,%3},{%4,%5,%6,%7},{%8,%9},{%0,%1,%2,%3};"
    :"+f"(c[0]),"+f"(c[1]),"+f"(c[2]),"+f"(c[3])
    :"r"(a[0]),"r"(a[1]),"r"(a[2]),"r"(a[3]),"r"(b0),"r"(b1));
}

// ---------------- generic small conv1d over L=512 (32-wide tiles) ----------------
template<int CI,int KS,bool RELU,bool SKIP>
__global__ void conv1d_small(const float* __restrict__ in,const float* __restrict__ w,
    const float* __restrict__ bias,const float* __restrict__ skip,
    float* __restrict__ out,int Cout){
  const int PAD=(KS-1)/2, WDT=32+KS-1;
  const int l0=blockIdx.x*32, cg=blockIdx.y, b=blockIdx.z;
  __shared__ float s[CI][WDT];
  for(int idx=threadIdx.x; idx<CI*WDT; idx+=256){
    int ci=idx/WDT, p=idx-ci*WDT, l=l0+p-PAD;
    s[ci][p]=(l>=0&&l<512)?in[(b*CI+ci)*512+l]:0.f;
  }
  __syncthreads();
  const int co=cg*64+(threadIdx.x>>2), ls=(threadIdx.x&3)*8;
  float acc[8]; float bz=bias[co];
#pragma unroll
  for(int j=0;j<8;j++)acc[j]=bz;
  const float* wr=w+(size_t)co*CI*KS;
  for(int ci=0;ci<CI;ci++){
    float xv[8+KS-1];
#pragma unroll
    for(int j=0;j<8+KS-1;j++)xv[j]=s[ci][ls+j];
#pragma unroll
    for(int k=0;k<KS;k++){
      float wv=__ldg(&wr[ci*KS+k]);
#pragma unroll
      for(int j=0;j<8;j++)acc[j]=fmaf(wv,xv[j+k],acc[j]);
    }
  }
  float* orow=out+((size_t)b*Cout+co)*512+l0+ls;
  const float* srow=SKIP?(skip+((size_t)b*Cout+co)*512+l0+ls):nullptr;
#pragma unroll
  for(int j=0;j<8;j++){
    float v=acc[j];
    if(RELU)v=lrelu(v);
    if(SKIP)v+=srow[j];
    orow[j]=v;
  }
}

// ---------------- build A' (im2col of h, hi/hi/lo) ----------------
__global__ void build_a16_k(){
  int idx=blockIdx.x*256+threadIdx.x;           // 8192*576
  int m=idx/576, kp=idx-m*576;
  int part=kp/192, kk=kp-part*192;
  int b=m>>9, l=m&511, hid=kk/3, t=kk-hid*3;
  int lp=l+t-1;
  float v=(lp>=0&&lp<512)?g_h[(b*64+hid)*512+lp]:0.f;
  __nv_bfloat16 hi=__float2bfloat16(v);
  g_a16[idx]=(part==2)?__float2bfloat16(v-__bfloat162float(hi)):hi;
}

// ---------------- build B' (ker_w, hi/lo/hi) ----------------
__global__ void build_b16_k(const float* __restrict__ kw){
  int idx=blockIdx.x*256+threadIdx.x;           // 24576*576
  int n=idx/576, kp=idx-n*576;
  int part=kp/192, kk=kp-part*192;
  float v=kw[(size_t)n*192+kk];
  __nv_bfloat16 hi=__float2bfloat16(v);
  g_b16[idx]=(part==1)?__float2bfloat16(v-__bfloat162float(hi)):hi;
}

// ---------------- mma.sync GEMM: g_kern = A'(8192x576) @ B'^T + ker_b ----------------
// CTA 128m x 256n, 256 threads, 8 warps (2m x 4n), warp tile 64x64.
// smem stage: A 128x64 bf16 (16KB) + B 256x64 bf16 (32KB); double buffered.
#define ST_SZ 49152
__global__ void __launch_bounds__(256,1) gemm_mma(const float* __restrict__ kerb){
  extern __shared__ __align__(128) char smem[];
  const uint32_t sb=smem_u32(smem);
  const int tid=threadIdx.x, lane=tid&31, wid=tid>>5;
  const int wm=wid&1, wn=wid>>1;
  const int m0=blockIdx.y*128, n0=blockIdx.x*256;

  float acc[4][8][4];
#pragma unroll
  for(int i=0;i<4;i++)
#pragma unroll
    for(int j=0;j<8;j++)
#pragma unroll
      for(int k=0;k<4;k++)acc[i][j][k]=0.f;

  auto load_stage=[&](int kc,int st){
    uint32_t abase=sb+st*ST_SZ, bbase=abase+16384;
#pragma unroll
    for(int i=0;i<4;i++){
      int q=tid+i*256, row=q>>3, c=q&7;
      cp16(abase+row*128+(((c^(row&7)))<<4),
           g_a16+(size_t)(m0+row)*576+kc*64+c*8);
    }
#pragma unroll
    for(int i=0;i<8;i++){
      int q=tid+i*256, row=q>>3, c=q&7;
      cp16(bbase+row*128+(((c^(row&7)))<<4),
           g_b16+(size_t)(n0+row)*576+kc*64+c*8);
    }
    asm volatile("cp.async.commit_group;");
  };

  load_stage(0,0);
  const int l7=lane&7;
  const int rAoff=l7+((lane>>3)&1)*8, cselA=lane>>4;
  const int rBoff=l7+((lane>>4)&1)*8, cselB=(lane>>3)&1;

  for(int kc=0;kc<9;kc++){
    if(kc<8) load_stage(kc+1,(kc+1)&1);
    if(kc<8) asm volatile("cp.async.wait_group 1;");
    else     asm volatile("cp.async.wait_group 0;");
    __syncthreads();
    uint32_t abase=sb+(kc&1)*ST_SZ, bbase=abase+16384;
#pragma unroll
    for(int ks=0;ks<4;ks++){
      const int c0=ks*2;
      uint32_t ar[4][4], br[4][4];
#pragma unroll
      for(int mi=0;mi<4;mi++){
        int row=wm*64+mi*16+rAoff;
        int cc=c0+cselA;
        ldmx4(ar[mi], abase+row*128+((cc^(row&7))<<4));
      }
#pragma unroll
      for(int np=0;np<4;np++){
        int row=wn*64+np*16+rBoff;
        int cc=c0+cselB;
        ldmx4(br[np], bbase+row*128+((cc^(row&7))<<4));
      }
#pragma unroll
      for(int mi=0;mi<4;mi++)
#pragma unroll
        for(int ni=0;ni<8;ni++)
          mma16816(acc[mi][ni], ar[mi], br[ni>>1][(ni&1)*2], br[ni>>1][(ni&1)*2+1]);
    }
    __syncthreads();
  }

  // epilogue: + ker_b -> g_kern
  const int g=lane>>2, t2=(lane&3)*2;
#pragma unroll
  for(int mi=0;mi<4;mi++){
    const int r0=m0+wm*64+mi*16+g;
    float* row0=g_kern+(size_t)r0*24576;
    float* row1=row0+(size_t)8*24576;
#pragma unroll
    for(int ni=0;ni<8;ni++){
      int col=n0+wn*64+ni*8+t2;
      float2 bb=*(const float2*)(kerb+col);
      float2 v0,v1;
      v0.x=acc[mi][ni][0]+bb.x; v0.y=acc[mi][ni][1]+bb.y;
      v1.x=acc[mi][ni][2]+bb.x; v1.y=acc[mi][ni][3]+bb.y;
      *(float2*)(row0+col)=v0;
      *(float2*)(row1+col)=v1;
    }
  }
}

// ---------------- convt_pre: lrelu(x) -> ConvTranspose1d(k=16, s=8, p=4) --------
__global__ void convt_pre_k(const float* __restrict__ x,const float* __restrict__ ctw,
    const float* __restrict__ ctb,float* __restrict__ xx){
  const int b=blockIdx.z, cg=blockIdx.y, t0=blockIdx.x*64, tid=threadIdx.x;
  __shared__ float swt[2048];
  __shared__ float sx[32][12];
  for(int idx=tid;idx<2048;idx+=256){
    int co_l=idx>>9, ci=(idx>>4)&31, kk=idx&15;
    swt[idx]=ctw[(ci*32+cg*4+co_l)*16+kk];
  }
  const int sbase=(t0>>3)-2;
  for(int idx=tid;idx<384;idx+=256){
    int ci=idx/12, j=idx-ci*12, sp=sbase+j;
    sx[ci][j]=(sp>=0&&sp<512)?lrelu(x[(b*32+ci)*512+sp]):0.f;
  }
  __syncthreads();
  const int co_l=tid>>6, t=t0+(tid&63), co=cg*4+co_l;
  const int k0=(8+(11-t)%8)&7;
  const int j=((t+k0-11)>>3)-sbase;
  float acc=ctb[co];
  const float* wl=&swt[co_l*512];
#pragma unroll 8
  for(int ci=0;ci<32;ci++)
    acc+=sx[ci][j]*wl[ci*16+15-k0]+sx[ci][j+1]*wl[ci*16+7-k0];
  xx[(b*32+co)*4096+t]=acc;
}

// ---------------- dilated conv block: g_cb = lrelu(conv(lrelu(xx))) ----------------
__global__ void conv_block_k(const float* __restrict__ xx,const float* __restrict__ w,
    const float* __restrict__ bias,int dil){
  const int b=blockIdx.z, t0=blockIdx.x*128, tid=threadIdx.x;
  __shared__ float sx[32*182];
  const int W=128+2*dil;
  for(int idx=tid;idx<32*W;idx+=256){
    int ci=idx/W, p=idx-ci*W, t=t0+p-dil;
    sx[ci*182+p]=(t>=0&&t<4096)?lrelu(xx[(b*32+ci)*4096+t]):0.f;
  }
  __syncthreads();
  const int co=tid>>3, lt=(tid&7)*16;
  float acc[16]; float bz=bias[co];
#pragma unroll
  for(int j=0;j<16;j++)acc[j]=bz;
  for(int ci=0;ci<32;ci++){
    float w0=__ldg(&w[(co*32+ci)*3]);
    float w1=__ldg(&w[(co*32+ci)*3+1]);
    float w2=__ldg(&w[(co*32+ci)*3+2]);
    const float* sr=&sx[ci*182+lt];
#pragma unroll
    for(int j=0;j<16;j++)
      acc[j]+=w0*sr[j]+w1*sr[j+dil]+w2*sr[j+2*dil];
  }
  float* orow=&g_cb[(b*32+co)*4096+t0+lt];
#pragma unroll
  for(int j=0;j<16;j++)orow[j]=lrelu(acc[j]);
}

// ---------------- LVC einsum + gated residual update ----------------
__global__ void einsum_gate_k(const float* __restrict__ kbias,float* __restrict__ xx,int layer){
  const int l=blockIdx.x, b=blockIdx.y, tid=threadIdx.x;
  __shared__ __align__(16) float sk[6144];
  __shared__ float sx[32][10];
  __shared__ float so[64][8];
  const float4* kp=(const float4*)(g_kern+((size_t)(b*512+l))*24576+layer*6144);
#pragma unroll
  for(int i=0;i<6;i++) ((float4*)sk)[tid+i*256]=kp[tid+i*256];
  for(int i=tid;i<320;i+=256){
    int ci=i/10, j=i-ci*10, t=l*8+j-1;
    sx[ci][j]=(t>=0&&t<4096)?g_cb[(b*32+ci)*4096+t]:0.f;
  }
  __syncthreads();
  const int o=tid>>2, h2=(tid&3)*2;
  float a0=0.f,a1=0.f;
#pragma unroll 4
  for(int ci=0;ci<32;ci++){
    const float* kb=&sk[ci*192+o*3];
    const float* xr=&sx[ci][h2];
    a0+=xr[0]*kb[0]+xr[1]*kb[1]+xr[2]*kb[2];
    a1+=xr[1]*kb[0]+xr[2]*kb[1]+xr[3]*kb[2];
  }
  const float bb=kbias[((b*4+layer)*64+o)*512+l];
  so[o][h2]=a0+bb; so[o][h2+1]=a1+bb;
  __syncthreads();
  const int co=tid>>3, h=tid&7;
  float g=1.f/(1.f+__expf(-so[co][h]));
  float th=tanhf(so[co+32][h]);
  xx[(b*32+co)*4096+l*8+h]+=g*th;
}

extern "C" void kernel_launch(void* const* d_in,const int* in_sizes,int n_in,
                              void* d_out,int out_size){
  const float* x     =(const float*)d_in[0];
  const float* c     =(const float*)d_in[1];
  const float* in_w  =(const float*)d_in[2];
  const float* in_b  =(const float*)d_in[3];
  const float* res_ws=(const float*)d_in[4];
  const float* res_bs=(const float*)d_in[5];
  const float* ker_w =(const float*)d_in[6];
  const float* ker_b =(const float*)d_in[7];
  const float* bias_w=(const float*)d_in[8];
  const float* bias_b=(const float*)d_in[9];
  const float* ct_w  =(const float*)d_in[10];
  const float* ct_b  =(const float*)d_in[11];
  const float* cb_ws =(const float*)d_in[12];
  const float* cb_bs =(const float*)d_in[13];
  float* xx=(float*)d_out;
  float *ph,*pr,*pkb;
  cudaGetSymbolAddress((void**)&ph, g_h);
  cudaGetSymbolAddress((void**)&pr, g_r);
  cudaGetSymbolAddress((void**)&pkb,g_kbias);

  cudaFuncSetAttribute(gemm_mma, cudaFuncAttributeMaxDynamicSharedMemorySize, 2*ST_SZ);

  // B' build can start immediately (independent of trunk)
  build_b16_k<<<55296,256>>>(ker_w);

  // kernel predictor trunk
  conv1d_small<100,5,true,false><<<dim3(16,1,16),256>>>(c,in_w,in_b,nullptr,ph,64);
  for(int j=0;j<3;j++){
    conv1d_small<64,3,true,false><<<dim3(16,1,16),256>>>(
        ph,res_ws+(size_t)(j*2)*12288,res_bs+(size_t)(j*2)*64,nullptr,pr,64);
    conv1d_small<64,3,true,true><<<dim3(16,1,16),256>>>(
        pr,res_ws+(size_t)(j*2+1)*12288,res_bs+(size_t)(j*2+1)*64,ph,ph,64);
  }
  // bias head
  conv1d_small<64,3,false,false><<<dim3(16,4,16),256>>>(ph,bias_w,bias_b,nullptr,pkb,256);
  // A' im2col
  build_a16_k<<<18432,256>>>();
  // tensor-core GEMM (portable mma.sync path; tcgen05 is gated off on this toolchain)
  gemm_mma<<<dim3(96,64),256,2*ST_SZ>>>(ker_b);
  // upsample
  convt_pre_k<<<dim3(64,8,16),256>>>(x,ct_w,ct_b,xx);
  // 4 LVC layers
  const int dils[4]={1,3,9,27};
  for(int i=0;i<4;i++){
    conv_block_k<<<dim3(32,1,16),256>>>(xx,cb_ws+(size_t)i*3072,cb_bs+(size_t)i*32,dils[i]);
    einsum_gate_k<<<dim3(512,16),256>>>(pkb,xx,i);
  }
}

// round 7
// speedup vs baseline: 1.6010x; 1.1148x over previous
#include <cuda_runtime.h>
#include <cuda_fp16.h>
#include <cstdint>

// ---------------- static device scratch ----------------
__device__ float g_h[16*64*512];
__device__ float g_r[16*64*512];
__device__ float g_kbias[16*256*512];
__device__ float g_kern[201326592];        // 8192 x 24576
__device__ float g_cb[16*32*4096];
__device__ __half g_a16[8192*192];         // A' = [Ah] fp16
__device__ __half g_b16[24576*384];        // B' = [Bh|Bl] fp16

__device__ __forceinline__ float lrelu(float v){ return v>=0.f ? v : 0.2f*v; }

__device__ __forceinline__ uint32_t smem_u32(const void* p){
  uint32_t a;
  asm("{ .reg .u64 t; cvta.to.shared.u64 t, %1; cvt.u32.u64 %0, t; }":"=r"(a):"l"(p));
  return a;
}
__device__ __forceinline__ void cp16(uint32_t d, const void* s){
  asm volatile("cp.async.cg.shared.global [%0], [%1], 16;"::"r"(d),"l"(s));
}
__device__ __forceinline__ void ldmx4(uint32_t* r, uint32_t a){
  asm volatile("ldmatrix.sync.aligned.m8n8.x4.shared.b16 {%0,%1,%2,%3},[%4];"
    :"=r"(r[0]),"=r"(r[1]),"=r"(r[2]),"=r"(r[3]):"r"(a));
}
__device__ __forceinline__ void mma16816(float* c, const uint32_t* a, uint32_t b0, uint32_t b1){
  asm volatile("mma.sync.aligned.m16n8k16.row.col.f32.f16.f16.f32 "
    "{%0,%1,%2,%3},{%4,%5,%6,%7},{%8,%9},{%0,%1,%2,%3};"
    :"+f"(c[0]),"+f"(c[1]),"+f"(c[2]),"+f"(c[3])
    :"r"(a[0]),"r"(a[1]),"r"(a[2]),"r"(a[3]),"r"(b0),"r"(b1));
}

// ---------------- generic small conv1d over L=512 (32-wide tiles) ----------------
template<int CI,int KS,bool RELU,bool SKIP>
__global__ void conv1d_small(const float* __restrict__ in,const float* __restrict__ w,
    const float* __restrict__ bias,const float* __restrict__ skip,
    float* __restrict__ out,int Cout){
  const int PAD=(KS-1)/2, WDT=32+KS-1;
  const int l0=blockIdx.x*32, cg=blockIdx.y, b=blockIdx.z;
  __shared__ float s[CI][WDT];
  for(int idx=threadIdx.x; idx<CI*WDT; idx+=256){
    int ci=idx/WDT, p=idx-ci*WDT, l=l0+p-PAD;
    s[ci][p]=(l>=0&&l<512)?in[(b*CI+ci)*512+l]:0.f;
  }
  __syncthreads();
  const int co=cg*64+(threadIdx.x>>2), ls=(threadIdx.x&3)*8;
  float acc[8]; float bz=bias[co];
#pragma unroll
  for(int j=0;j<8;j++)acc[j]=bz;
  const float* wr=w+(size_t)co*CI*KS;
  for(int ci=0;ci<CI;ci++){
    float xv[8+KS-1];
#pragma unroll
    for(int j=0;j<8+KS-1;j++)xv[j]=s[ci][ls+j];
#pragma unroll
    for(int k=0;k<KS;k++){
      float wv=__ldg(&wr[ci*KS+k]);
#pragma unroll
      for(int j=0;j<8;j++)acc[j]=fmaf(wv,xv[j+k],acc[j]);
    }
  }
  float* orow=out+((size_t)b*Cout+co)*512+l0+ls;
  const float* srow=SKIP?(skip+((size_t)b*Cout+co)*512+l0+ls):nullptr;
#pragma unroll
  for(int j=0;j<8;j++){
    float v=acc[j];
    if(RELU)v=lrelu(v);
    if(SKIP)v+=srow[j];
    orow[j]=v;
  }
}

// ---------------- build A' (im2col of h -> fp16 hi) ----------------
__global__ void build_a16_k(){
  int idx=blockIdx.x*256+threadIdx.x;           // 8192*192
  int m=idx/192, kk=idx-m*192;
  int b=m>>9, l=m&511, hid=kk/3, t=kk-hid*3;
  int lp=l+t-1;
  float v=(lp>=0&&lp<512)?g_h[(b*64+hid)*512+lp]:0.f;
  g_a16[idx]=__float2half_rn(v);
}

// ---------------- build B' (ker_w -> fp16 hi/lo, width 384) ----------------
__global__ void build_b16_k(const float* __restrict__ kw){
  int idx=blockIdx.x*256+threadIdx.x;           // 24576*384
  int n=idx/384, kp=idx-n*384;
  int part=(kp>=192), kk=kp-(part?192:0);
  float v=kw[(size_t)n*192+kk];
  __half hi=__float2half_rn(v);
  g_b16[idx]=part?__float2half_rn(v-__half2float(hi)):hi;
}

// ---------------- mma.sync GEMM, fp16 2-pass: Ah*Bh + Ah*Bl -----------------------
// CTA 128m x 256n, 8 warps (2m x 4n), warp tile 64x64; K'=384, 6 chunks of 64.
// A chunk col = (kc%3)*64 (A' width 192), B chunk col = kc*64 (B' width 384).
#define ST_SZ 49152
__global__ void __launch_bounds__(256,1) gemm_mma(const float* __restrict__ kerb){
  extern __shared__ __align__(128) char smem[];
  const uint32_t sb=smem_u32(smem);
  const int tid=threadIdx.x, lane=tid&31, wid=tid>>5;
  const int wm=wid&1, wn=wid>>1;
  const int m0=blockIdx.y*128, n0=blockIdx.x*256;

  float acc[4][8][4];
#pragma unroll
  for(int i=0;i<4;i++)
#pragma unroll
    for(int j=0;j<8;j++)
#pragma unroll
      for(int k=0;k<4;k++)acc[i][j][k]=0.f;

  auto load_stage=[&](int kc,int st){
    uint32_t abase=sb+st*ST_SZ, bbase=abase+16384;
    const int acol=(kc%3)*64;
#pragma unroll
    for(int i=0;i<4;i++){
      int q=tid+i*256, row=q>>3, c=q&7;
      cp16(abase+row*128+(((c^(row&7)))<<4),
           g_a16+(size_t)(m0+row)*192+acol+c*8);
    }
#pragma unroll
    for(int i=0;i<8;i++){
      int q=tid+i*256, row=q>>3, c=q&7;
      cp16(bbase+row*128+(((c^(row&7)))<<4),
           g_b16+(size_t)(n0+row)*384+kc*64+c*8);
    }
    asm volatile("cp.async.commit_group;");
  };

  load_stage(0,0);
  const int l7=lane&7;
  const int rAoff=l7+((lane>>3)&1)*8, cselA=lane>>4;
  const int rBoff=l7+((lane>>4)&1)*8, cselB=(lane>>3)&1;

  for(int kc=0;kc<6;kc++){
    if(kc<5) load_stage(kc+1,(kc+1)&1);
    if(kc<5) asm volatile("cp.async.wait_group 1;");
    else     asm volatile("cp.async.wait_group 0;");
    __syncthreads();
    uint32_t abase=sb+(kc&1)*ST_SZ, bbase=abase+16384;
#pragma unroll
    for(int ks=0;ks<4;ks++){
      const int c0=ks*2;
      uint32_t ar[4][4], br[4][4];
#pragma unroll
      for(int mi=0;mi<4;mi++){
        int row=wm*64+mi*16+rAoff;
        int cc=c0+cselA;
        ldmx4(ar[mi], abase+row*128+((cc^(row&7))<<4));
      }
#pragma unroll
      for(int np=0;np<4;np++){
        int row=wn*64+np*16+rBoff;
        int cc=c0+cselB;
        ldmx4(br[np], bbase+row*128+((cc^(row&7))<<4));
      }
#pragma unroll
      for(int mi=0;mi<4;mi++)
#pragma unroll
        for(int ni=0;ni<8;ni++)
          mma16816(acc[mi][ni], ar[mi], br[ni>>1][(ni&1)*2], br[ni>>1][(ni&1)*2+1]);
    }
    __syncthreads();
  }

  // epilogue: + ker_b -> g_kern
  const int g=lane>>2, t2=(lane&3)*2;
#pragma unroll
  for(int mi=0;mi<4;mi++){
    const int r0=m0+wm*64+mi*16+g;
    float* row0=g_kern+(size_t)r0*24576;
    float* row1=row0+(size_t)8*24576;
#pragma unroll
    for(int ni=0;ni<8;ni++){
      int col=n0+wn*64+ni*8+t2;
      float2 bb=*(const float2*)(kerb+col);
      float2 v0,v1;
      v0.x=acc[mi][ni][0]+bb.x; v0.y=acc[mi][ni][1]+bb.y;
      v1.x=acc[mi][ni][2]+bb.x; v1.y=acc[mi][ni][3]+bb.y;
      *(float2*)(row0+col)=v0;
      *(float2*)(row1+col)=v1;
    }
  }
}

// ---------------- convt_pre: lrelu(x) -> ConvTranspose1d(k=16, s=8, p=4) --------
__global__ void convt_pre_k(const float* __restrict__ x,const float* __restrict__ ctw,
    const float* __restrict__ ctb,float* __restrict__ xx){
  const int b=blockIdx.z, cg=blockIdx.y, t0=blockIdx.x*64, tid=threadIdx.x;
  __shared__ float swt[2048];
  __shared__ float sx[32][12];
  for(int idx=tid;idx<2048;idx+=256){
    int co_l=idx>>9, ci=(idx>>4)&31, kk=idx&15;
    swt[idx]=ctw[(ci*32+cg*4+co_l)*16+kk];
  }
  const int sbase=(t0>>3)-2;
  for(int idx=tid;idx<384;idx+=256){
    int ci=idx/12, j=idx-ci*12, sp=sbase+j;
    sx[ci][j]=(sp>=0&&sp<512)?lrelu(x[(b*32+ci)*512+sp]):0.f;
  }
  __syncthreads();
  const int co_l=tid>>6, t=t0+(tid&63), co=cg*4+co_l;
  const int k0=(8+(11-t)%8)&7;
  const int j=((t+k0-11)>>3)-sbase;
  float acc=ctb[co];
  const float* wl=&swt[co_l*512];
#pragma unroll 8
  for(int ci=0;ci<32;ci++)
    acc+=sx[ci][j]*wl[ci*16+15-k0]+sx[ci][j+1]*wl[ci*16+7-k0];
  xx[(b*32+co)*4096+t]=acc;
}

// ---------------- dilated conv block ----------------
__global__ void conv_block_k(const float* __restrict__ xx,const float* __restrict__ w,
    const float* __restrict__ bias,int dil){
  const int b=blockIdx.z, t0=blockIdx.x*128, tid=threadIdx.x;
  __shared__ float sx[32*182];
  const int W=128+2*dil;
  for(int idx=tid;idx<32*W;idx+=256){
    int ci=idx/W, p=idx-ci*W, t=t0+p-dil;
    sx[ci*182+p]=(t>=0&&t<4096)?lrelu(xx[(b*32+ci)*4096+t]):0.f;
  }
  __syncthreads();
  const int co=tid>>3, lt=(tid&7)*16;
  float acc[16]; float bz=bias[co];
#pragma unroll
  for(int j=0;j<16;j++)acc[j]=bz;
  for(int ci=0;ci<32;ci++){
    float w0=__ldg(&w[(co*32+ci)*3]);
    float w1=__ldg(&w[(co*32+ci)*3+1]);
    float w2=__ldg(&w[(co*32+ci)*3+2]);
    const float* sr=&sx[ci*182+lt];
#pragma unroll
    for(int j=0;j<16;j++)
      acc[j]+=w0*sr[j]+w1*sr[j+dil]+w2*sr[j+2*dil];
  }
  float* orow=&g_cb[(b*32+co)*4096+t0+lt];
#pragma unroll
  for(int j=0;j<16;j++)orow[j]=lrelu(acc[j]);
}

// ---------------- LVC einsum + gated residual update ----------------
__global__ void einsum_gate_k(const float* __restrict__ kbias,float* __restrict__ xx,int layer){
  const int l=blockIdx.x, b=blockIdx.y, tid=threadIdx.x;
  __shared__ __align__(16) float sk[6144];
  __shared__ float sx[32][10];
  __shared__ float so[64][8];
  const float4* kp=(const float4*)(g_kern+((size_t)(b*512+l))*24576+layer*6144);
#pragma unroll
  for(int i=0;i<6;i++) ((float4*)sk)[tid+i*256]=kp[tid+i*256];
  for(int i=tid;i<320;i+=256){
    int ci=i/10, j=i-ci*10, t=l*8+j-1;
    sx[ci][j]=(t>=0&&t<4096)?g_cb[(b*32+ci)*4096+t]:0.f;
  }
  __syncthreads();
  const int o=tid>>2, h2=(tid&3)*2;
  float a0=0.f,a1=0.f;
#pragma unroll 4
  for(int ci=0;ci<32;ci++){
    const float* kb=&sk[ci*192+o*3];
    const float* xr=&sx[ci][h2];
    a0+=xr[0]*kb[0]+xr[1]*kb[1]+xr[2]*kb[2];
    a1+=xr[1]*kb[0]+xr[2]*kb[1]+xr[3]*kb[2];
  }
  const float bb=kbias[((b*4+layer)*64+o)*512+l];
  so[o][h2]=a0+bb; so[o][h2+1]=a1+bb;
  __syncthreads();
  const int co=tid>>3, h=tid&7;
  float g=1.f/(1.f+__expf(-so[co][h]));
  float th=tanhf(so[co+32][h]);
  xx[(b*32+co)*4096+l*8+h]+=g*th;
}

extern "C" void kernel_launch(void* const* d_in,const int* in_sizes,int n_in,
                              void* d_out,int out_size){
  const float* x     =(const float*)d_in[0];
  const float* c     =(const float*)d_in[1];
  const float* in_w  =(const float*)d_in[2];
  const float* in_b  =(const float*)d_in[3];
  const float* res_ws=(const float*)d_in[4];
  const float* res_bs=(const float*)d_in[5];
  const float* ker_w =(const float*)d_in[6];
  const float* ker_b =(const float*)d_in[7];
  const float* bias_w=(const float*)d_in[8];
  const float* bias_b=(const float*)d_in[9];
  const float* ct_w  =(const float*)d_in[10];
  const float* ct_b  =(const float*)d_in[11];
  const float* cb_ws =(const float*)d_in[12];
  const float* cb_bs =(const float*)d_in[13];
  float* xx=(float*)d_out;
  float *ph,*pr,*pkb;
  cudaGetSymbolAddress((void**)&ph, g_h);
  cudaGetSymbolAddress((void**)&pr, g_r);
  cudaGetSymbolAddress((void**)&pkb,g_kbias);

  cudaFuncSetAttribute(gemm_mma, cudaFuncAttributeMaxDynamicSharedMemorySize, 2*ST_SZ);

  // B' build can start immediately (independent of trunk)
  build_b16_k<<<36864,256>>>(ker_w);

  // kernel predictor trunk (R4-proven: SKIP convs keep h resident in g_h)
  conv1d_small<100,5,true,false><<<dim3(16,1,16),256>>>(c,in_w,in_b,nullptr,ph,64);
  for(int j=0;j<3;j++){
    conv1d_small<64,3,true,false><<<dim3(16,1,16),256>>>(
        ph,res_ws+(size_t)(j*2)*12288,res_bs+(size_t)(j*2)*64,nullptr,pr,64);
    conv1d_small<64,3,true,true><<<dim3(16,1,16),256>>>(
        pr,res_ws+(size_t)(j*2+1)*12288,res_bs+(size_t)(j*2+1)*64,ph,ph,64);
  }
  // bias head
  conv1d_small<64,3,false,false><<<dim3(16,4,16),256>>>(ph,bias_w,bias_b,nullptr,pkb,256);
  // A' im2col
  build_a16_k<<<6144,256>>>();
  // tensor-core GEMM (fp16 2-pass)
  gemm_mma<<<dim3(96,64),256,2*ST_SZ>>>(ker_b);
  // upsample
  convt_pre_k<<<dim3(64,8,16),256>>>(x,ct_w,ct_b,xx);
  // 4 LVC layers
  const int dils[4]={1,3,9,27};
  for(int i=0;i<4;i++){
    conv_block_k<<<dim3(32,1,16),256>>>(xx,cb_ws+(size_t)i*3072,cb_bs+(size_t)i*32,dils[i]);
    einsum_gate_k<<<dim3(512,16),256>>>(pkb,xx,i);
  }
}